// round 4
// baseline (speedup 1.0000x reference)
#include <cuda_runtime.h>

// SWAP gate, DIM=2, C=0, T=1, WIRES=12 -> D=4096, BATCH=1024.
// out[k, :] = x[swap_bits_10_11(k), :] for both planes (involution).
// Row bits 10/11 == flat float4-index bits 18/19 (256 float4 per row).
//
// Bandwidth kernel. Stores use .cs (streaming / evict-first) so the
// output write-stream does not evict the L2-resident inputs across
// graph replays; steady-state DRAM traffic then is the write stream only.

#define D_DIM   4096
#define BATCH   1024
#define VEC_PER_ROW (BATCH / 4)          // 256 float4 per row
#define TOTAL_VEC (D_DIM * VEC_PER_ROW)  // 1,048,576 float4 per plane

__device__ __forceinline__ void stg_cs(float4* p, float4 v) {
    asm volatile("st.global.cs.v4.f32 [%0], {%1, %2, %3, %4};"
                 :: "l"(p), "f"(v.x), "f"(v.y), "f"(v.z), "f"(v.w)
                 : "memory");
}

__global__ void __launch_bounds__(256) swap_gather_kernel(
    const float4* __restrict__ xr,
    const float4* __restrict__ xi,
    float4* __restrict__ out)   // [2, D, BATCH] as float4
{
    unsigned idx = blockIdx.x * blockDim.x + threadIdx.x;  // 0 .. TOTAL_VEC-1

    // swap bits 18 and 19 of the flat float4 index (== row bits 10/11)
    unsigned diff = ((idx >> 18) ^ (idx >> 19)) & 1u;
    unsigned src  = idx ^ (diff * 0xC0000u);

    float4 r = __ldg(xr + src);
    float4 i = __ldg(xi + src);
    stg_cs(out + idx, r);
    stg_cs(out + TOTAL_VEC + idx, i);
}

extern "C" void kernel_launch(void* const* d_in, const int* in_sizes, int n_in,
                              void* d_out, int out_size) {
    const float4* xr = (const float4*)d_in[0];
    const float4* xi = (const float4*)d_in[1];
    // d_in[2] = U (permutation matrix) — closed form, unused.
    float4* out = (float4*)d_out;

    dim3 grid(TOTAL_VEC / 256);   // 4096 blocks
    dim3 block(256);
    swap_gather_kernel<<<grid, block>>>(xr, xi, out);
}